// round 17
// baseline (speedup 1.0000x reference)
#include <cuda_runtime.h>
#include <cuda_bf16.h>

// GraphConvOp: out[b,t,v,f] = sum_e [rows[e]==v] * vals[e] * in[b,t,cols[e],f]
// B=2, T=16 (BT=32), V=10000, F=32, NNZ=160000. rows sorted.
// Intrinsic gather traffic NNZ*BT*F*4B = 655MB served from L1/L2 (~17TB/s
// effective measured in R2 -> near service ceiling). This build is a SINGLE
// kernel: each block binary-searches its row segment in the sorted rows[]
// (2 x ~17 dependent loads, hidden by 10000-block parallelism), eliminating
// the prelude kernel + its serialized graph node.

#define V_NODES 10000
#define F_DIM   32
#define BT      32
#define EDGE_CHUNK 128

__device__ __forceinline__ int lower_bound_dev(const int* __restrict__ a,
                                               int n, int key) {
    int lo = 0, hi = n;
    while (lo < hi) {
        int mid = (lo + hi) >> 1;
        if (__ldg(a + mid) < key) lo = mid + 1; else hi = mid;
    }
    return lo;
}

// grid = V blocks (one row each), 256 threads (8 warps). Warp w owns
// bt-slices [4w, 4w+4); lane: bt_sub = lane>>3, f4 = lane&7 (8 float4 = F=32).
// Per edge a warp issues 4 coalesced 128B gathers (L1/L2-resident).
// 8-edge unroll -> 8 outstanding gathers per warp for latency hiding.
__global__ __launch_bounds__(256, 4)
void spmm_kernel(const float* __restrict__ x,
                 const float* __restrict__ vals,
                 const int*   __restrict__ rows,
                 const int*   __restrict__ cols,
                 float*       __restrict__ out,
                 int nnz)
{
    __shared__ int   s_bounds[2];       // [start, end] of this row's segment
    __shared__ int   s_cols[EDGE_CHUNK];
    __shared__ float s_vals[EDGE_CHUNK];

    const int v    = blockIdx.x;
    const int warp = threadIdx.x >> 5;
    const int lane = threadIdx.x & 31;
    const int bt   = warp * 4 + (lane >> 3);
    const int f4   = lane & 7;

    // Two threads find the segment bounds; rest of block proceeds after sync.
    if (threadIdx.x < 2)
        s_bounds[threadIdx.x] = lower_bound_dev(rows, nnz, v + threadIdx.x);
    __syncthreads();
    const int start = s_bounds[0];
    const int end   = s_bounds[1];

    // x viewed as float4: element (bt, col, f4) at (bt*V + col)*8 + f4
    const float4* __restrict__ xb =
        reinterpret_cast<const float4*>(x) + (size_t)bt * V_NODES * 8 + f4;

    float4 acc = make_float4(0.f, 0.f, 0.f, 0.f);

    for (int base = start; base < end; base += EDGE_CHUNK) {
        const int n = min(EDGE_CHUNK, end - base);
        // cooperative stage of this row's edge list (one pass for deg<=128)
        for (int i = threadIdx.x; i < n; i += 256) {
            s_cols[i] = cols[base + i];
            s_vals[i] = vals[base + i];
        }
        __syncthreads();

        int i = 0;
        // 8-edge unroll: batch 8 independent gathers, then FMA chain.
        for (; i + 8 <= n; i += 8) {
            float4 g[8];
            float  w[8];
#pragma unroll
            for (int k = 0; k < 8; ++k) {
                int c = s_cols[i + k];
                w[k]  = s_vals[i + k];
                g[k]  = __ldg(xb + (size_t)c * 8);
            }
#pragma unroll
            for (int k = 0; k < 8; ++k) {
                acc.x = fmaf(w[k], g[k].x, acc.x);
                acc.y = fmaf(w[k], g[k].y, acc.y);
                acc.z = fmaf(w[k], g[k].z, acc.z);
                acc.w = fmaf(w[k], g[k].w, acc.w);
            }
        }
        for (; i < n; ++i) {
            int   c  = s_cols[i];
            float wv = s_vals[i];
            float4 xx = __ldg(xb + (size_t)c * 8);
            acc.x = fmaf(wv, xx.x, acc.x); acc.y = fmaf(wv, xx.y, acc.y);
            acc.z = fmaf(wv, xx.z, acc.z); acc.w = fmaf(wv, xx.w, acc.w);
        }
        __syncthreads();
    }

    float4* __restrict__ ob =
        reinterpret_cast<float4*>(out) + ((size_t)bt * V_NODES + v) * 8 + f4;
    *ob = acc;  // zero-degree rows write zeros (d_out is poisoned, must init)
}

extern "C" void kernel_launch(void* const* d_in, const int* in_sizes, int n_in,
                              void* d_out, int out_size) {
    const float* x    = (const float*)d_in[0];   // inputs [B,T,V,F] f32
    const float* vals = (const float*)d_in[1];   // L_vals [NNZ] f32
    const int*   rows = (const int*)  d_in[2];   // L_rows [NNZ] i32 (sorted)
    const int*   cols = (const int*)  d_in[3];   // L_cols [NNZ] i32
    float*       out  = (float*)d_out;
    const int nnz = in_sizes[1];

    spmm_kernel<<<V_NODES, 256>>>(x, vals, rows, cols, out, nnz);
}